// round 1
// baseline (speedup 1.0000x reference)
#include <cuda_runtime.h>
#include <cuda_bf16.h>
#include <cstdint>

// ExpertScatter: out[b, Ind[b,h,k], :] += Y[b,h,k,:] @ W[h]
// Shapes: Y[8,16,1024,128] f32, Ind[8,16,1024] i32, W[16,128,1024] f32,
//         out[8,4096,1024] f32.
// Round 1 baseline: fused fp32 tiled GEMM + atomic scatter.

#define BB     8
#define HH     16
#define KDIM   1024
#define DD     128      // head_dim (reduction)
#define NN     1024     // out_dim
#define TT     4096

#define TM     128      // rows per CTA tile
#define TN     128      // cols per n-chunk
#define NCHUNK (NN / TN)   // 8
#define YS_STRIDE 132   // padded to dodge transpose-store bank conflicts
#define THREADS 256

#define SMEM_BYTES ((DD * YS_STRIDE + DD * TN) * (int)sizeof(float))  // 133,120 B

__global__ void zero_out_kernel(float4* __restrict__ p, int n4) {
    int i = blockIdx.x * blockDim.x + threadIdx.x;
    if (i < n4) p[i] = make_float4(0.f, 0.f, 0.f, 0.f);
}

__global__ void __launch_bounds__(THREADS, 1)
expert_scatter_kernel(const float* __restrict__ Y,
                      const int*   __restrict__ Ind,
                      const float* __restrict__ W,
                      float*       __restrict__ out) {
    const int b  = blockIdx.z;
    const int h  = blockIdx.y;
    const int k0 = blockIdx.x * TM;

    extern __shared__ float sm[];
    float* Ys = sm;                     // [DD][YS_STRIDE]  Y tile, k-major (transposed)
    float* Ws = sm + DD * YS_STRIDE;    // [DD][TN]         W chunk, k-major
    __shared__ int sInd[TM];

    const int tid = threadIdx.x;
    const int tm  = tid >> 4;    // 0..15 -> m0 = tm*8
    const int tn  = tid & 15;    // 0..15 -> n0 = tn*8
    const int m0  = tm * 8;
    const int n0  = tn * 8;

    // ---- Load Y tile [TM x DD] into smem transposed as Ys[j][m] ----
    const float* Yp = Y + ((size_t)(b * HH + h) * KDIM + k0) * DD;
    #pragma unroll
    for (int idx = tid; idx < TM * (DD / 4); idx += THREADS) {
        const int m  = idx >> 5;        // DD/4 = 32 float4 per row
        const int j4 = idx & 31;
        const float4 v = *(const float4*)(Yp + (size_t)m * DD + j4 * 4);
        const int j = j4 * 4;
        Ys[(j + 0) * YS_STRIDE + m] = v.x;
        Ys[(j + 1) * YS_STRIDE + m] = v.y;
        Ys[(j + 2) * YS_STRIDE + m] = v.z;
        Ys[(j + 3) * YS_STRIDE + m] = v.w;
    }
    if (tid < TM) sInd[tid] = Ind[(size_t)(b * HH + h) * KDIM + k0 + tid];

    const float* Wh = W + (size_t)h * DD * NN;
    const size_t ob = (size_t)b * TT * NN;

    for (int nc = 0; nc < NCHUNK; nc++) {
        __syncthreads();   // prev chunk done reading Ws (and Ys/sInd visible on nc==0 path via next sync)

        // ---- Load W chunk [DD x TN] into Ws[j][n] ----
        #pragma unroll
        for (int idx = tid; idx < DD * (TN / 4); idx += THREADS) {
            const int j  = idx >> 5;    // TN/4 = 32 float4 per row
            const int c4 = idx & 31;
            const float4 v = *(const float4*)(Wh + (size_t)j * NN + nc * TN + c4 * 4);
            *(float4*)(Ws + j * TN + c4 * 4) = v;
        }
        __syncthreads();

        // ---- 8x8 register microtile GEMM over k = 0..127 ----
        float acc[8][8];
        #pragma unroll
        for (int i = 0; i < 8; i++)
            #pragma unroll
            for (int jj = 0; jj < 8; jj++) acc[i][jj] = 0.f;

        #pragma unroll 4
        for (int kk = 0; kk < DD; kk++) {
            const float4 a0 = *(const float4*)(Ys + kk * YS_STRIDE + m0);
            const float4 a1 = *(const float4*)(Ys + kk * YS_STRIDE + m0 + 4);
            const float4 b0 = *(const float4*)(Ws + kk * TN + n0);
            const float4 b1 = *(const float4*)(Ws + kk * TN + n0 + 4);
            const float av[8] = {a0.x, a0.y, a0.z, a0.w, a1.x, a1.y, a1.z, a1.w};
            const float bv[8] = {b0.x, b0.y, b0.z, b0.w, b1.x, b1.y, b1.z, b1.w};
            #pragma unroll
            for (int i = 0; i < 8; i++)
                #pragma unroll
                for (int jj = 0; jj < 8; jj++)
                    acc[i][jj] = fmaf(av[i], bv[jj], acc[i][jj]);
        }

        // ---- Atomic scatter of this chunk ----
        #pragma unroll
        for (int i = 0; i < 8; i++) {
            const int t = sInd[m0 + i];
            float* dst = out + ob + (size_t)t * NN + nc * TN + n0;
            #pragma unroll
            for (int jj = 0; jj < 8; jj++)
                atomicAdd(dst + jj, acc[i][jj]);
        }
    }
}

extern "C" void kernel_launch(void* const* d_in, const int* in_sizes, int n_in,
                              void* d_out, int out_size) {
    const float* Y   = (const float*)d_in[0];
    const int*   Ind = (const int*)d_in[1];
    const float* W   = (const float*)d_in[n_in - 1];   // W is the last input (Y, Ind, T, W)
    float* out = (float*)d_out;

    // zero-initialize the (0xAA-poisoned) output
    const int n4 = (BB * TT * NN) / 4;
    zero_out_kernel<<<(n4 + 255) / 256, 256>>>((float4*)out, n4);

    cudaFuncSetAttribute(expert_scatter_kernel,
                         cudaFuncAttributeMaxDynamicSharedMemorySize, SMEM_BYTES);
    dim3 grid(KDIM / TM, HH, BB);   // 8 x 16 x 8 = 1024 CTAs
    expert_scatter_kernel<<<grid, THREADS, SMEM_BYTES>>>(Y, Ind, W, out);
}

// round 2
// speedup vs baseline: 1.9025x; 1.9025x over previous
#include <cuda_runtime.h>
#include <cuda_bf16.h>
#include <cstdint>

// ExpertScatter: out[b, Ind[b,h,k], :] += Y[b,h,k,:] @ W[h]
// Y[8,16,1024,128] f32, Ind[8,16,1024] i32, W[16,128,1024] f32, out[8,4096,1024] f32.
// R2: tf32 mma.sync tensor-core GEMM, fragment-order smem staging, red.v2 scatter.

#define BB     8
#define HH     16
#define KDIM   1024
#define DD     128      // reduction dim
#define NN     1024     // out cols
#define TT     4096

#define TM     256      // rows per CTA
#define TN     128      // cols per n-chunk
#define NCHUNK (NN / TN)      // 8
#define THREADS 256
#define KS     (DD / 8)       // 16 k-steps of k8

// smem: As = TM*DD tf32 (fragment order) = 128KB ; Bs = DD*TN = 64KB
#define AS_WORDS (TM * DD)        // 32768 u32
#define BS_WORDS (DD * TN)        // 16384 u32
#define SMEM_BYTES ((AS_WORDS + BS_WORDS) * 4)   // 196608

__global__ void zero_out_kernel(float4* __restrict__ p, int n4) {
    int i = blockIdx.x * blockDim.x + threadIdx.x;
    if (i < n4) p[i] = make_float4(0.f, 0.f, 0.f, 0.f);
}

__device__ __forceinline__ uint32_t f2tf32(float f) {
    uint32_t r;
    asm("cvt.rna.tf32.f32 %0, %1;" : "=r"(r) : "f"(f));
    return r;
}

__device__ __forceinline__ void mma_tf32(float* c, const uint4 a, const uint2 bf) {
    asm volatile(
        "mma.sync.aligned.m16n8k8.row.col.f32.tf32.tf32.f32 "
        "{%0,%1,%2,%3}, {%4,%5,%6,%7}, {%8,%9}, {%0,%1,%2,%3};"
        : "+f"(c[0]), "+f"(c[1]), "+f"(c[2]), "+f"(c[3])
        : "r"(a.x), "r"(a.y), "r"(a.z), "r"(a.w), "r"(bf.x), "r"(bf.y));
}

__device__ __forceinline__ void red_v2(float* p, float x, float y) {
    asm volatile("red.global.add.v2.f32 [%0], {%1, %2};"
                 :: "l"(p), "f"(x), "f"(y) : "memory");
}

__global__ void __launch_bounds__(THREADS, 1)
expert_scatter_tc(const float* __restrict__ Y,
                  const int*   __restrict__ Ind,
                  const float* __restrict__ W,
                  float*       __restrict__ out) {
    const int b  = blockIdx.z;
    const int h  = blockIdx.y;
    const int k0 = blockIdx.x * TM;

    extern __shared__ uint32_t sm[];
    uint32_t* As = sm;               // [tile16(16)][ks(16)][lane(32)] x uint4 frag
    uint32_t* Bs = sm + AS_WORDS;    // [wn*8+in(16)][ks(16)][lane(32)] x uint2 frag
    __shared__ int sInd[TM];

    const int tid  = threadIdx.x;
    const int warp = tid >> 5;
    const int lane = tid & 31;
    const int g    = lane >> 2;      // groupID
    const int tig  = lane & 3;       // thread-in-group
    const int wm   = warp >> 1;      // 0..3 : 64-row band
    const int wn   = warp & 1;       // 0..1 : 64-col band

    // ---- Stage Y tile [TM x DD] into As in mma-fragment order (tf32) ----
    const float* Yp = Y + ((size_t)(b * HH + h) * KDIM + k0) * DD;
    #pragma unroll
    for (int idx = tid; idx < TM * (DD / 4); idx += THREADS) {   // 8192 float4
        const int m  = idx >> 5;
        const int k4 = idx & 31;
        const float4 v = *(const float4*)(Yp + (size_t)m * DD + k4 * 4);
        const int tile16 = m >> 4;
        const int r  = m & 15;
        const int gg = r & 7;
        const int hi = r >> 3;
        const int ks = k4 >> 1;
        const int sel = k4 & 1;
        const int comp = hi + (sel << 1);
        // slot(lane) = ((tile16*16+ks)*32 + gg*4 + t)  ; uint index = slot*4 + comp
        uint32_t* base = As + (((tile16 * 16 + ks) * 32 + (gg << 2)) << 2) + comp;
        base[0]  = f2tf32(v.x);
        base[4]  = f2tf32(v.y);
        base[8]  = f2tf32(v.z);
        base[12] = f2tf32(v.w);
    }
    if (tid < TM) sInd[tid] = Ind[(size_t)(b * HH + h) * KDIM + k0 + tid];
    __syncthreads();

    // per-warp output row indices (fixed across chunks)
    int t0s[4], t1s[4];
    #pragma unroll
    for (int im = 0; im < 4; im++) {
        const int mrow = wm * 64 + im * 16;
        t0s[im] = sInd[mrow + g];
        t1s[im] = sInd[mrow + g + 8];
    }

    const float* Wh  = W + (size_t)h * DD * NN;
    float* outb = out + (size_t)b * TT * NN;

    #pragma unroll 1
    for (int nc = 0; nc < NCHUNK; nc++) {
        // ---- Stage W chunk [DD x TN] into Bs in fragment order (tf32) ----
        #pragma unroll
        for (int idx = tid; idx < DD * (TN / 4); idx += THREADS) {  // 4096 float4
            const int k  = idx >> 5;
            const int n  = (idx & 31) * 4;
            const float4 v = *(const float4*)(Wh + (size_t)k * NN + nc * TN + n);
            const int wnn = n >> 6;
            const int nl  = n & 63;
            const int in  = nl >> 3;
            const int gg  = nl & 7;           // 0 or 4 (n % 4 == 0)
            const int ks  = k >> 3;
            const int kk  = k & 7;
            const int tg  = kk & 3;
            const int sel = kk >> 2;
            // slot = ((wnn*8+in)*16+ks)*32 + (gg+e)*4 + tg ; uint idx = slot*2 + sel
            uint32_t* base = Bs + ((((wnn * 8 + in) * 16 + ks) * 32 + (gg << 2) + tg) << 1) + sel;
            base[0]  = f2tf32(v.x);
            base[8]  = f2tf32(v.y);   // lane +4 -> uint +8
            base[16] = f2tf32(v.z);
            base[24] = f2tf32(v.w);
        }
        __syncthreads();

        // ---- 64x64 warp tile GEMM: 4(im) x 8(in) x 16(ks) mma ----
        float acc[4][8][4];
        #pragma unroll
        for (int im = 0; im < 4; im++)
            #pragma unroll
            for (int in = 0; in < 8; in++)
                #pragma unroll
                for (int c = 0; c < 4; c++) acc[im][in][c] = 0.f;

        const uint4* Af = (const uint4*)As;
        const uint2* Bf = (const uint2*)Bs;
        #pragma unroll
        for (int ks = 0; ks < KS; ks++) {
            uint4 a[4];
            #pragma unroll
            for (int im = 0; im < 4; im++)
                a[im] = Af[((wm * 4 + im) * 16 + ks) * 32 + lane];
            #pragma unroll
            for (int in = 0; in < 8; in++) {
                const uint2 bf = Bf[((wn * 8 + in) * 16 + ks) * 32 + lane];
                #pragma unroll
                for (int im = 0; im < 4; im++)
                    mma_tf32(acc[im][in], a[im], bf);
            }
        }

        // ---- scatter this chunk via vectorized global reductions ----
        const int colb = nc * TN + wn * 64 + tig * 2;
        #pragma unroll
        for (int im = 0; im < 4; im++) {
            float* r0 = outb + (size_t)t0s[im] * NN + colb;
            float* r1 = outb + (size_t)t1s[im] * NN + colb;
            #pragma unroll
            for (int in = 0; in < 8; in++) {
                red_v2(r0 + in * 8, acc[im][in][0], acc[im][in][1]);
                red_v2(r1 + in * 8, acc[im][in][2], acc[im][in][3]);
            }
        }
        __syncthreads();   // all warps done reading Bs before next chunk overwrite
    }
}

extern "C" void kernel_launch(void* const* d_in, const int* in_sizes, int n_in,
                              void* d_out, int out_size) {
    const float* Y   = (const float*)d_in[0];
    const int*   Ind = (const int*)d_in[1];
    const float* W   = (const float*)d_in[n_in - 1];
    float* out = (float*)d_out;

    const int n4 = (BB * TT * NN) / 4;
    zero_out_kernel<<<(n4 + 255) / 256, 256>>>((float4*)out, n4);

    cudaFuncSetAttribute(expert_scatter_tc,
                         cudaFuncAttributeMaxDynamicSharedMemorySize, SMEM_BYTES);
    dim3 grid(KDIM / TM, HH, BB);   // 4 x 16 x 8 = 512 CTAs
    expert_scatter_tc<<<grid, THREADS, SMEM_BYTES>>>(Y, Ind, W, out);
}

// round 4
// speedup vs baseline: 2.9725x; 1.5624x over previous
#include <cuda_runtime.h>
#include <cstdint>

// ExpertScatter: out[b, Ind[b,h,k], :] += Y[b,h,k,:] @ W[h]
// Y[8,16,1024,128] f32, Ind[8,16,1024] i32, W[16,128,1024] f32, out[8,4096,1024] f32
// R4: mma.sync tf32 (compute_103-safe), 512-thread CTA (16 warps), swizzled
//     conflict-free fragment staging, red.global.add.v2 scatter.

#define BB 8
#define HH 16
#define KDIM 1024
#define DD 128
#define NN 1024
#define TT 4096

#define TM 256
#define TN 128
#define NCHUNK 8
#define THREADS 512
#define KS 16

#define AS_WORDS (TM * DD)   // 32768 u32 = 128KB
#define BS_WORDS (DD * TN)   // 16384 u32 = 64KB
#define SMEM_BYTES ((AS_WORDS + BS_WORDS) * 4)   // 196608

__global__ void zero_out_kernel(float4* __restrict__ p, int n4) {
    int i = blockIdx.x * blockDim.x + threadIdx.x;
    if (i < n4) p[i] = make_float4(0.f, 0.f, 0.f, 0.f);
}

__device__ __forceinline__ uint32_t f2tf32(float f) {
    uint32_t r; asm("cvt.rna.tf32.f32 %0, %1;" : "=r"(r) : "f"(f)); return r;
}
__device__ __forceinline__ void mma_tf32(float* c, const uint4 a, const uint2 b) {
    asm volatile(
        "mma.sync.aligned.m16n8k8.row.col.f32.tf32.tf32.f32 "
        "{%0,%1,%2,%3}, {%4,%5,%6,%7}, {%8,%9}, {%0,%1,%2,%3};"
        : "+f"(c[0]), "+f"(c[1]), "+f"(c[2]), "+f"(c[3])
        : "r"(a.x), "r"(a.y), "r"(a.z), "r"(a.w), "r"(b.x), "r"(b.y));
}
__device__ __forceinline__ void red_v2(float* p, float x, float y) {
    asm volatile("red.global.add.v2.f32 [%0], {%1, %2};"
                 :: "l"(p), "f"(x), "f"(y) : "memory");
}

__global__ void __launch_bounds__(THREADS, 1)
expert_scatter_tc(const float* __restrict__ Y,
                  const int*   __restrict__ Ind,
                  const float* __restrict__ W,
                  float*       __restrict__ out) {
    const int b  = blockIdx.z;
    const int h  = blockIdx.y;
    const int k0 = blockIdx.x * TM;

    extern __shared__ uint32_t sm[];
    uint32_t* As = sm;                 // fragment order, ks-swizzled
    uint32_t* Bs = sm + AS_WORDS;      // fragment order, ks-swizzled
    __shared__ int sInd[TM];

    const int tid  = threadIdx.x;
    const int warp = tid >> 5;
    const int lane = tid & 31;
    const int g    = lane >> 2;
    const int tig  = lane & 3;
    const int wm   = warp >> 2;   // 0..3 : 64-row band
    const int wn   = warp & 3;    // 0..3 : 32-col band

    // ---- Stage A: Y tile [256m x 128k] -> tf32 fragments, swizzled ----
    // lane -> k4 (flat&31): per-warp m fixed, k varies -> swizzle spreads banks
    const float* Yp = Y + ((size_t)(b * HH + h) * KDIM + k0) * DD;
    #pragma unroll
    for (int i = 0; i < 16; i++) {
        const int flat = i * THREADS + tid;
        const int m  = flat >> 5;
        const int k4 = flat & 31;
        const float4 v = *(const float4*)(Yp + (size_t)m * DD + k4 * 4);
        const int tile16 = m >> 4;
        const int r   = m & 15;
        const int gg  = r & 7;
        const int hi  = r >> 3;
        const int ks  = k4 >> 1;
        const int sel = k4 & 1;
        const int comp = hi + (sel << 1);
        const uint32_t base = ((uint32_t)(tile16 * 16 + ks)) * 32;
        const uint32_t sz = (uint32_t)(ks & 7);
        uint32_t wv[4] = { f2tf32(v.x), f2tf32(v.y), f2tf32(v.z), f2tf32(v.w) };
        #pragma unroll
        for (int e = 0; e < 4; e++) {
            const uint32_t slot = (uint32_t)((gg << 2) + e) ^ sz;
            As[(base + slot) * 4 + comp] = wv[e];
        }
    }
    if (tid < TM) sInd[tid] = Ind[(size_t)(b * HH + h) * KDIM + k0 + tid];
    __syncthreads();

    // per-warp scatter row indices (fixed across chunks)
    int t0s[4], t1s[4];
    #pragma unroll
    for (int im = 0; im < 4; im++) {
        const int mrow = wm * 64 + im * 16;
        t0s[im] = sInd[mrow + g];
        t1s[im] = sInd[mrow + g + 8];
    }

    const float* Wh  = W + (size_t)h * DD * NN;
    float* outb = out + (size_t)b * TT * NN;

    #pragma unroll 1
    for (int nc = 0; nc < NCHUNK; nc++) {
        // ---- Stage B chunk: W[k, nc*128+n] -> tf32 fragments, swizzled ----
        // lane -> klo: store side conflict-free with (ks&3)<<2 swizzle
        #pragma unroll
        for (int i = 0; i < 8; i++) {
            const int flat = i * THREADS + tid;
            const int klo  = flat & 31;
            const int rest = flat >> 5;        // 0..127
            const int n4   = rest & 31;
            const int khi  = rest >> 5;        // 0..3
            const int k    = khi * 32 + klo;
            const float4 v = *(const float4*)(Wh + (size_t)k * NN + nc * TN + n4 * 4);
            const int ks  = k >> 3;
            const int kk  = k & 7;
            const int tg  = kk & 3;
            const int sel = kk >> 2;
            const uint32_t sz = (uint32_t)((ks & 3) << 2);
            const float vv[4] = { v.x, v.y, v.z, v.w };
            #pragma unroll
            for (int e = 0; e < 4; e++) {
                const int n  = n4 * 4 + e;
                const int nt = n >> 3;
                const int gg = n & 7;
                const uint32_t slot = (uint32_t)((gg << 2) + tg) ^ sz;
                Bs[((uint32_t)(nt * 16 + ks) * 32 + slot) * 2 + sel] = f2tf32(vv[e]);
            }
        }
        __syncthreads();

        // ---- Warp tile 64m x 32n: 4(im) x 4(in) x 16(ks) mma ----
        float acc[4][4][4];
        #pragma unroll
        for (int im = 0; im < 4; im++)
            #pragma unroll
            for (int in = 0; in < 4; in++)
                #pragma unroll
                for (int c = 0; c < 4; c++) acc[im][in][c] = 0.f;

        const uint4* Af = (const uint4*)As;
        const uint2* Bf = (const uint2*)Bs;
        #pragma unroll
        for (int ks = 0; ks < KS; ks++) {
            const int laneA = lane ^ (ks & 7);
            const int laneB = lane ^ ((ks & 3) << 2);
            uint4 a[4];
            #pragma unroll
            for (int im = 0; im < 4; im++)
                a[im] = Af[((wm * 4 + im) * 16 + ks) * 32 + laneA];
            #pragma unroll
            for (int in = 0; in < 4; in++) {
                const uint2 bf = Bf[((wn * 4 + in) * 16 + ks) * 32 + laneB];
                #pragma unroll
                for (int im = 0; im < 4; im++)
                    mma_tf32(acc[im][in], a[im], bf);
            }
        }

        // ---- Scatter chunk via vectorized global reductions ----
        const int colb = nc * TN + wn * 32 + tig * 2;
        #pragma unroll
        for (int im = 0; im < 4; im++) {
            float* r0 = outb + (size_t)t0s[im] * NN + colb;
            float* r1 = outb + (size_t)t1s[im] * NN + colb;
            #pragma unroll
            for (int in = 0; in < 4; in++) {
                red_v2(r0 + in * 8, acc[im][in][0], acc[im][in][1]);
                red_v2(r1 + in * 8, acc[im][in][2], acc[im][in][3]);
            }
        }
        __syncthreads();   // Bs reuse barrier
    }
}

extern "C" void kernel_launch(void* const* d_in, const int* in_sizes, int n_in,
                              void* d_out, int out_size) {
    const float* Y   = (const float*)d_in[0];
    const int*   Ind = (const int*)d_in[1];
    const float* W   = (const float*)d_in[n_in - 1];
    float* out = (float*)d_out;

    const int n4 = (BB * TT * NN) / 4;
    zero_out_kernel<<<(n4 + 511) / 512, 512>>>((float4*)out, n4);

    cudaFuncSetAttribute(expert_scatter_tc,
                         cudaFuncAttributeMaxDynamicSharedMemorySize, SMEM_BYTES);
    dim3 grid(KDIM / TM, HH, BB);   // 4 x 16 x 8 = 512 CTAs
    expert_scatter_tc<<<grid, THREADS, SMEM_BYTES>>>(Y, Ind, W, out);
}